// round 10
// baseline (speedup 1.0000x reference)
#include <cuda_runtime.h>
#include <cuda_fp16.h>
#include <stdint.h>

#define BATCH 32
#define CIN   128
#define HH    56
#define WW    56
#define COUT  256
#define HP    58
#define NPIX  (HH*WW)            // 3136
#define IMGB  (HP*HP*CIN)        // padded image elements

// ---------------- scratch (device globals) ----------------------------------
__device__ __half g_qx[BATCH*HP*HP*CIN];   // padded NHWC, quantized ints as fp16
__device__ __half g_qw[9*COUT*CIN];        // [tap][co][ci] as fp16
__device__ float  g_px[1024];
__device__ float  g_pw[64];
__device__ float  g_scale_x, g_dq;

// ---------------- helpers -----------------------------------------------------
__device__ __forceinline__ uint32_t smem_u32(const void* p) {
    uint32_t a;
    asm("{ .reg .u64 t; cvta.to.shared.u64 t, %1; cvt.u32.u64 %0, t; }" : "=r"(a) : "l"(p));
    return a;
}
#define SW128(o) ((o) ^ (((o) >> 3) & 0x70))

__device__ __forceinline__ void cp16(uint32_t dst, const void* src) {
    asm volatile("cp.async.cg.shared.global [%0], [%1], 16;" :: "r"(dst), "l"(src) : "memory");
}
#define CP_COMMIT()  asm volatile("cp.async.commit_group;" ::: "memory")
#define CP_WAIT(n)   asm volatile("cp.async.wait_group %0;" :: "n"(n) : "memory")

__device__ __forceinline__ void ldsm_x4(unsigned* r, uint32_t addr) {
    asm volatile("ldmatrix.sync.aligned.m8n8.x4.shared.b16 {%0,%1,%2,%3}, [%4];"
        : "=r"(r[0]), "=r"(r[1]), "=r"(r[2]), "=r"(r[3]) : "r"(addr));
}

// fp16 HMMA: m16n8k16, A row-major, B col-major, f32 accumulate
__device__ __forceinline__ void hmma16816(float* d, const unsigned* a, const unsigned* b) {
    asm volatile("mma.sync.aligned.m16n8k16.row.col.f32.f16.f16.f32 "
        "{%0,%1,%2,%3}, {%4,%5,%6,%7}, {%8,%9}, {%0,%1,%2,%3};"
        : "+f"(d[0]), "+f"(d[1]), "+f"(d[2]), "+f"(d[3])
        : "r"(a[0]), "r"(a[1]), "r"(a[2]), "r"(a[3]), "r"(b[0]), "r"(b[1]));
}

__device__ __forceinline__ float warp_red_max(float m) {
    #pragma unroll
    for (int o = 16; o; o >>= 1) m = fmaxf(m, __shfl_xor_sync(0xffffffffu, m, o));
    return m;
}

// ---------------- 0: partial amax --------------------------------------------
__global__ void k_part(const float4* __restrict__ x, const float4* __restrict__ w) {
    int blk = blockIdx.x;
    const float4* p; int n4, stride, start;
    if (blk < 1024) { p = x; n4 = BATCH*CIN*HH*WW/4; start = blk*256 + threadIdx.x; stride = 1024*256; }
    else            { p = w; n4 = COUT*CIN*9/4;      start = (blk-1024)*256 + threadIdx.x; stride = 64*256; }
    float m = 0.f;
    for (int i = start; i < n4; i += stride) {
        float4 v = p[i];
        m = fmaxf(m, fmaxf(fmaxf(fabsf(v.x), fabsf(v.y)), fmaxf(fabsf(v.z), fabsf(v.w))));
    }
    m = warp_red_max(m);
    __shared__ float sm[8];
    int lane = threadIdx.x & 31, wid = threadIdx.x >> 5;
    if (lane == 0) sm[wid] = m;
    __syncthreads();
    if (wid == 0) {
        m = (lane < 8) ? sm[lane] : 0.f;
        m = warp_red_max(m);
        if (lane == 0) { if (blk < 1024) g_px[blk] = m; else g_pw[blk-1024] = m; }
    }
}

// ---------------- 1: finalize scales + quantize weights (store fp16) ---------
__global__ void k_quant_w(const float* __restrict__ wt) {
    __shared__ float s_sw;
    {
        float mx = 0.f, mw = 0.f;
        for (int i = threadIdx.x; i < 1024; i += blockDim.x) mx = fmaxf(mx, g_px[i]);
        if (threadIdx.x < 64) mw = g_pw[threadIdx.x];
        mx = warp_red_max(mx); mw = warp_red_max(mw);
        __shared__ float smx[8], smw[8];
        int lane = threadIdx.x & 31, wid = threadIdx.x >> 5;
        if (lane == 0) { smx[wid] = mx; smw[wid] = mw; }
        __syncthreads();
        if (threadIdx.x == 0) {
            float ax = 0.f, aw = 0.f;
            #pragma unroll
            for (int i = 0; i < 8; i++) { ax = fmaxf(ax, smx[i]); aw = fmaxf(aw, smw[i]); }
            float sx = __fdiv_rn(127.0f, ax);
            float sw = __fdiv_rn(127.0f, aw);
            s_sw = sw;
            if (blockIdx.x == 0) {
                g_scale_x = sx;
                g_dq = __fdiv_rn(1.0f, __fmul_rn(sx, sw));
            }
        }
        __syncthreads();
    }
    float sc = s_sw;
    const int n = 9*COUT*CIN;
    for (int o = blockIdx.x*blockDim.x + threadIdx.x; o < n; o += gridDim.x*blockDim.x) {
        int ci  = o & 127;
        int co  = (o >> 7) & 255;
        int tap = o >> 15;
        float q = rintf(wt[(co*CIN + ci)*9 + tap] * sc);
        q = fminf(fmaxf(q, -127.f), 127.f);
        g_qw[o] = __float2half_rn(q);       // |q|<=127: exact in fp16
    }
}

// ---------------- 2: quantize x into padded NHWC (store fp16) -----------------
__global__ void k_quant_x(const float* __restrict__ x) {
    int b = blockIdx.x / HP, hp = blockIdx.x % HP;
    __half* dst = g_qx + ((size_t)b*HP + hp)*HP*CIN;
    if (hp == 0 || hp == HP-1) {
        for (int e = threadIdx.x; e < HP*CIN/8; e += blockDim.x)
            ((int4*)dst)[e] = make_int4(0,0,0,0);
        return;
    }
    int h = hp - 1;
    __shared__ __half s[CIN][60];
    float sc = g_scale_x;
    const float* base = x + ((size_t)b*CIN*HH + h)*WW;
    for (int e = threadIdx.x; e < CIN*WW; e += blockDim.x) {
        int c = e / WW, w = e - c*WW;
        float q = rintf(base[(size_t)c*HH*WW + w] * sc);
        q = fminf(fmaxf(q, -127.f), 127.f);
        s[c][w] = __float2half_rn(q);
    }
    __syncthreads();
    for (int e = threadIdx.x; e < HP*CIN; e += blockDim.x) {
        int wp = e >> 7, c = e & 127;
        dst[e] = (wp == 0 || wp == HP-1) ? __float2half_rn(0.f) : s[c][wp-1];
    }
}

// ---------------- 3: fp16 HMMA implicit-GEMM conv, ldmatrix fragments ---------
// CTA: 128 px x 128 co, 256 thr = 8 warps (4m x 2n); warp tile 32px x 64co.
// K = 9 taps x 128 ci, chunked at 64 ci; cp.async double-buffered.
// Fragments via ldmatrix.x4: per ks, 2 LDSM (A) + 4 LDSM (B) + 16 HMMA.
#define STAGE 32768
#define SMEM_TOTAL 65536

__global__ void __launch_bounds__(256, 2) k_conv(const float* __restrict__ bias,
                                                 float* __restrict__ out) {
    extern __shared__ char smem[];
    uint32_t sb = smem_u32(smem);
    float* s_out = (float*)smem;

    int tid = threadIdx.x;
    int wid = tid >> 5, lane = tid & 31;
    int wm = wid & 3, wn = wid >> 2;            // 4 x 2 warp grid
    int g = lane >> 2, tg = lane & 3;

    int tile   = blockIdx.x;                    // 0..24
    int coBase = blockIdx.y << 7;               // 0 or 128
    int bimg   = blockIdx.z;
    int p0 = tile * 128;

    // ---- ldmatrix per-lane geometry (row in tile, seg index, xor mask) ----
    int rr = lane & 7;
    // A x4: lanes 0-15 -> rows 0-15 seg(ks,0); lanes 16-31 -> rows seg(ks,1)
    uint32_t aRow = (uint32_t)(wm*32 + ((lane >> 3) & 1)*8 + rr);   // + mt*16
    uint32_t aSeg = (uint32_t)(lane >> 4);                          // 0/1
    // B x4 (nt pair): lanes 0-7 rows n0+0..7 s0; 8-15 same rows s1;
    //                 16-23 rows n0+8..15 s0; 24-31 s1
    uint32_t bRow = (uint32_t)(wn*64 + (lane >> 4)*8 + rr);         // + pair*16
    uint32_t bSeg = (uint32_t)((lane >> 3) & 1);

    // producer: thread t loads row r = t>>1, 4x16B segs starting at (t&1)*4
    int r = tid >> 1, s4 = (tid & 1) << 2;
    int p = min(p0 + r, NPIX-1);
    int ph = p / WW, pw = p - ph*WW;
    const __half* qb = g_qx + (size_t)bimg * IMGB;
    const __half* abase = qb + (ph*HP + pw)*CIN;
    const __half* wbase = g_qw + (size_t)(coBase + r)*CIN;
    uint32_t dA[4], dB[4];
    #pragma unroll
    for (int i = 0; i < 4; i++) {
        uint32_t o = SW128((uint32_t)(r*128 + (s4+i)*16));
        dA[i] = o; dB[i] = 16384 + o;
    }

    float acc[2][8][4];
    #pragma unroll
    for (int mt = 0; mt < 2; mt++)
        #pragma unroll
        for (int nt = 0; nt < 8; nt++)
            #pragma unroll
            for (int q = 0; q < 4; q++) acc[mt][nt][q] = 0.f;

    // prefetch chunk 0 (tap 0, khalf 0) into stage 0
    #pragma unroll
    for (int i = 0; i < 4; i++) {
        cp16(sb + dA[i], abase + (s4+i)*8);
        cp16(sb + dB[i], wbase + (s4+i)*8);
    }
    CP_COMMIT();

    for (int ch = 0; ch < 18; ch++) {
        if (ch < 17) {
            int nc = ch + 1;
            int tap = nc >> 1, kh2 = nc & 1;
            int dh = tap / 3, dw = tap - dh*3;
            const __half* as = abase + (dh*HP + dw)*CIN + kh2*64;
            const __half* ws = wbase + (size_t)tap*COUT*CIN + kh2*64;
            uint32_t stg = sb + ((nc & 1) ? STAGE : 0);
            #pragma unroll
            for (int i = 0; i < 4; i++) {
                cp16(stg + dA[i], as + (s4+i)*8);
                cp16(stg + dB[i], ws + (s4+i)*8);
            }
            CP_COMMIT();
            CP_WAIT(1);
        } else {
            CP_WAIT(0);
        }
        __syncthreads();

        uint32_t stgA = sb + ((ch & 1) ? STAGE : 0), stgB = stgA + 16384;
        uint32_t aBase = stgA + aRow*128;       // + mt*2048 + swizzled seg
        uint32_t bBase = stgB + bRow*128;       // + pair*2048

        #pragma unroll
        for (int ks = 0; ks < 4; ks++) {        // 4 x k16 per 64-ci chunk
            uint32_t aSw = (uint32_t)((((ks << 1) | aSeg) ^ rr) << 4);
            uint32_t bSw = (uint32_t)((((ks << 1) | bSeg) ^ rr) << 4);
            unsigned bf[4][4];                  // [pair][b0,b1 of nt, b0,b1 of nt+1]
            #pragma unroll
            for (int pr = 0; pr < 4; pr++)
                ldsm_x4(bf[pr], bBase + (uint32_t)pr*2048 + bSw);
            #pragma unroll
            for (int mt = 0; mt < 2; mt++) {
                unsigned af[4];
                ldsm_x4(af, aBase + (uint32_t)mt*2048 + aSw);
                #pragma unroll
                for (int pr = 0; pr < 4; pr++) {
                    hmma16816(acc[mt][pr*2],     af, &bf[pr][0]);
                    hmma16816(acc[mt][pr*2 + 1], af, &bf[pr][2]);
                }
            }
        }
        __syncthreads();
    }

    // ---- epilogue: stage [64co][132px] in smem, coalesced dequant+bias stores
    float dq = g_dq;
    int rro = tid >> 7;             // 0..1
    int px = tid & 127;
    bool pv = (p0 + px) < NPIX;
    float* obase = out + ((size_t)bimg*COUT + coBase)*NPIX + p0 + px;

    #pragma unroll
    for (int pass = 0; pass < 2; pass++) {
        if (wn == pass) {
            #pragma unroll
            for (int mt = 0; mt < 2; mt++) {
                int px0 = wm*32 + mt*16 + g;
                #pragma unroll
                for (int nt = 0; nt < 8; nt++) {
                    int cl = nt*8 + tg*2;
                    s_out[cl*132 + px0]         = acc[mt][nt][0] * dq;
                    s_out[(cl+1)*132 + px0]     = acc[mt][nt][1] * dq;
                    s_out[cl*132 + px0 + 8]     = acc[mt][nt][2] * dq;
                    s_out[(cl+1)*132 + px0 + 8] = acc[mt][nt][3] * dq;
                }
            }
        }
        __syncthreads();
        if (pv) {
            #pragma unroll 8
            for (int it = 0; it < 32; it++) {
                int row = it*2 + rro;
                int co = pass*64 + row;
                obase[(size_t)co * NPIX] = s_out[row*132 + px] + __ldg(&bias[coBase + co]);
            }
        }
        __syncthreads();
    }
}

// ---------------- launch ------------------------------------------------------
extern "C" void kernel_launch(void* const* d_in, const int* in_sizes, int n_in,
                              void* d_out, int out_size) {
    const float* x    = (const float*)d_in[0];
    const float* wt   = (const float*)d_in[1];
    const float* bias = (const float*)d_in[2];
    float* out = (float*)d_out;

    cudaFuncSetAttribute(k_conv, cudaFuncAttributeMaxDynamicSharedMemorySize, SMEM_TOTAL);

    k_part<<<1088, 256>>>((const float4*)x, (const float4*)wt);   // idx 0
    k_quant_w<<<288, 256>>>(wt);                                  // idx 1
    k_quant_x<<<BATCH*HP, 256>>>(x);                              // idx 2
    dim3 grid(25, 2, BATCH);
    k_conv<<<grid, 256, SMEM_TOTAL>>>(bias, out);                 // idx 3 (ncu)
    (void)in_sizes; (void)n_in; (void)out_size;
}

// round 11
// speedup vs baseline: 1.1175x; 1.1175x over previous
#include <cuda_runtime.h>
#include <cuda_fp16.h>
#include <stdint.h>

#define BATCH 32
#define CIN   128
#define HH    56
#define WW    56
#define COUT  256
#define HP    58
#define NPIX  (HH*WW)            // 3136
#define IMGB  (HP*HP*CIN)        // padded image elements

// ---------------- scratch (device globals) ----------------------------------
__device__ __half g_qx[BATCH*HP*HP*CIN];   // padded NHWC, quantized ints as fp16
__device__ __half g_qw[9*COUT*CIN];        // [tap][co][ci] as fp16
__device__ float  g_px[1024];
__device__ float  g_pw[64];
__device__ float  g_scale_x, g_dq;

// ---------------- helpers -----------------------------------------------------
__device__ __forceinline__ uint32_t smem_u32(const void* p) {
    uint32_t a;
    asm("{ .reg .u64 t; cvta.to.shared.u64 t, %1; cvt.u32.u64 %0, t; }" : "=r"(a) : "l"(p));
    return a;
}
#define SW128(o) ((o) ^ (((o) >> 3) & 0x70))

__device__ __forceinline__ void cp16(uint32_t dst, const void* src) {
    asm volatile("cp.async.cg.shared.global [%0], [%1], 16;" :: "r"(dst), "l"(src) : "memory");
}
#define CP_COMMIT()  asm volatile("cp.async.commit_group;" ::: "memory")
#define CP_WAIT(n)   asm volatile("cp.async.wait_group %0;" :: "n"(n) : "memory")

__device__ __forceinline__ unsigned lds32(uint32_t a) {
    unsigned v; asm volatile("ld.shared.b32 %0, [%1];" : "=r"(v) : "r"(a)); return v;
}

// fp16 HMMA: m16n8k16, A row-major, B col-major, f32 accumulate
__device__ __forceinline__ void hmma16816(float* d, const unsigned* a, const unsigned* b) {
    asm volatile("mma.sync.aligned.m16n8k16.row.col.f32.f16.f16.f32 "
        "{%0,%1,%2,%3}, {%4,%5,%6,%7}, {%8,%9}, {%0,%1,%2,%3};"
        : "+f"(d[0]), "+f"(d[1]), "+f"(d[2]), "+f"(d[3])
        : "r"(a[0]), "r"(a[1]), "r"(a[2]), "r"(a[3]), "r"(b[0]), "r"(b[1]));
}

__device__ __forceinline__ float warp_red_max(float m) {
    #pragma unroll
    for (int o = 16; o; o >>= 1) m = fmaxf(m, __shfl_xor_sync(0xffffffffu, m, o));
    return m;
}

// ---------------- 0: partial amax --------------------------------------------
__global__ void k_part(const float4* __restrict__ x, const float4* __restrict__ w) {
    int blk = blockIdx.x;
    const float4* p; int n4, stride, start;
    if (blk < 1024) { p = x; n4 = BATCH*CIN*HH*WW/4; start = blk*256 + threadIdx.x; stride = 1024*256; }
    else            { p = w; n4 = COUT*CIN*9/4;      start = (blk-1024)*256 + threadIdx.x; stride = 64*256; }
    float m = 0.f;
    for (int i = start; i < n4; i += stride) {
        float4 v = p[i];
        m = fmaxf(m, fmaxf(fmaxf(fabsf(v.x), fabsf(v.y)), fmaxf(fabsf(v.z), fabsf(v.w))));
    }
    m = warp_red_max(m);
    __shared__ float sm[8];
    int lane = threadIdx.x & 31, wid = threadIdx.x >> 5;
    if (lane == 0) sm[wid] = m;
    __syncthreads();
    if (wid == 0) {
        m = (lane < 8) ? sm[lane] : 0.f;
        m = warp_red_max(m);
        if (lane == 0) { if (blk < 1024) g_px[blk] = m; else g_pw[blk-1024] = m; }
    }
}

// ---------------- 1: finalize scales + quantize weights (store fp16) ---------
__global__ void k_quant_w(const float* __restrict__ wt) {
    __shared__ float s_sw;
    {
        float mx = 0.f, mw = 0.f;
        for (int i = threadIdx.x; i < 1024; i += blockDim.x) mx = fmaxf(mx, g_px[i]);
        if (threadIdx.x < 64) mw = g_pw[threadIdx.x];
        mx = warp_red_max(mx); mw = warp_red_max(mw);
        __shared__ float smx[8], smw[8];
        int lane = threadIdx.x & 31, wid = threadIdx.x >> 5;
        if (lane == 0) { smx[wid] = mx; smw[wid] = mw; }
        __syncthreads();
        if (threadIdx.x == 0) {
            float ax = 0.f, aw = 0.f;
            #pragma unroll
            for (int i = 0; i < 8; i++) { ax = fmaxf(ax, smx[i]); aw = fmaxf(aw, smw[i]); }
            float sx = __fdiv_rn(127.0f, ax);
            float sw = __fdiv_rn(127.0f, aw);
            s_sw = sw;
            if (blockIdx.x == 0) {
                g_scale_x = sx;
                g_dq = __fdiv_rn(1.0f, __fmul_rn(sx, sw));
            }
        }
        __syncthreads();
    }
    float sc = s_sw;
    const int n = 9*COUT*CIN;
    for (int o = blockIdx.x*blockDim.x + threadIdx.x; o < n; o += gridDim.x*blockDim.x) {
        int ci  = o & 127;
        int co  = (o >> 7) & 255;
        int tap = o >> 15;
        float q = rintf(wt[(co*CIN + ci)*9 + tap] * sc);
        q = fminf(fmaxf(q, -127.f), 127.f);
        g_qw[o] = __float2half_rn(q);       // |q|<=127: exact in fp16
    }
}

// ---------------- 2: quantize x into padded NHWC (store fp16) -----------------
__global__ void k_quant_x(const float* __restrict__ x) {
    int b = blockIdx.x / HP, hp = blockIdx.x % HP;
    __half* dst = g_qx + ((size_t)b*HP + hp)*HP*CIN;
    if (hp == 0 || hp == HP-1) {
        for (int e = threadIdx.x; e < HP*CIN/8; e += blockDim.x)
            ((int4*)dst)[e] = make_int4(0,0,0,0);
        return;
    }
    int h = hp - 1;
    __shared__ __half s[CIN][60];
    float sc = g_scale_x;
    const float* base = x + ((size_t)b*CIN*HH + h)*WW;
    for (int e = threadIdx.x; e < CIN*WW; e += blockDim.x) {
        int c = e / WW, w = e - c*WW;
        float q = rintf(base[(size_t)c*HH*WW + w] * sc);
        q = fminf(fmaxf(q, -127.f), 127.f);
        s[c][w] = __float2half_rn(q);
    }
    __syncthreads();
    for (int e = threadIdx.x; e < HP*CIN; e += blockDim.x) {
        int wp = e >> 7, c = e & 127;
        dst[e] = (wp == 0 || wp == HP-1) ? __float2half_rn(0.f) : s[c][wp-1];
    }
}

// ---------------- 3: fp16 HMMA conv, 32 warps/SM -------------------------------
// CTA: 128 px x 128 co, 512 thr = 16 warps (4m x 4n); warp tile 32px x 32co.
// acc = 32 floats -> <=64 regs -> 2 CTAs/SM = 32 warps/SM (8 per SMSP).
// K = 9 taps x 128 ci, chunked at 64 ci; cp.async double-buffered.
#define STAGE 32768
#define SMEM_TOTAL 65536

__global__ void __launch_bounds__(512, 2) k_conv(const float* __restrict__ bias,
                                                 float* __restrict__ out) {
    extern __shared__ char smem[];
    uint32_t sb = smem_u32(smem);
    float* s_out = (float*)smem;

    int tid = threadIdx.x;
    int wid = tid >> 5, lane = tid & 31;
    int wm = wid & 3, wn = wid >> 2;            // 4 x 4 warp grid
    int g = lane >> 2, tg = lane & 3;

    int tile   = blockIdx.x;                    // 0..24
    int coBase = blockIdx.y << 7;               // 0 or 128
    int bimg   = blockIdx.z;
    int p0 = tile * 128;

    // producer: thread t -> row r = t>>2, two 16B segs at (t&3)*2, +1
    int r = tid >> 2, s2 = (tid & 3) << 1;
    int p = min(p0 + r, NPIX-1);
    int ph = p / WW, pw = p - ph*WW;
    const __half* qb = g_qx + (size_t)bimg * IMGB;
    const __half* abase = qb + (ph*HP + pw)*CIN;
    const __half* wbase = g_qw + (size_t)(coBase + r)*CIN;
    uint32_t dA[2], dB[2];
    #pragma unroll
    for (int i = 0; i < 2; i++) {
        uint32_t o = SW128((uint32_t)(r*128 + (s2+i)*16));
        dA[i] = o; dB[i] = 16384 + o;
    }

    float acc[2][4][4];
    #pragma unroll
    for (int mt = 0; mt < 2; mt++)
        #pragma unroll
        for (int nt = 0; nt < 4; nt++)
            #pragma unroll
            for (int q = 0; q < 4; q++) acc[mt][nt][q] = 0.f;

    // prefetch chunk 0 (tap 0, khalf 0) into stage 0
    #pragma unroll
    for (int i = 0; i < 2; i++) {
        cp16(sb + dA[i], abase + (s2+i)*8);
        cp16(sb + dB[i], wbase + (s2+i)*8);
    }
    CP_COMMIT();

    for (int ch = 0; ch < 18; ch++) {
        if (ch < 17) {
            int nc = ch + 1;
            int tap = nc >> 1, kh2 = nc & 1;
            int dh = tap / 3, dw = tap - dh*3;
            const __half* as = abase + (dh*HP + dw)*CIN + kh2*64;
            const __half* ws = wbase + (size_t)tap*COUT*CIN + kh2*64;
            uint32_t stg = sb + ((nc & 1) ? STAGE : 0);
            #pragma unroll
            for (int i = 0; i < 2; i++) {
                cp16(stg + dA[i], as + (s2+i)*8);
                cp16(stg + dB[i], ws + (s2+i)*8);
            }
            CP_COMMIT();
            CP_WAIT(1);
        } else {
            CP_WAIT(0);
        }
        __syncthreads();

        uint32_t stgA = sb + ((ch & 1) ? STAGE : 0), stgB = stgA + 16384;
        #pragma unroll
        for (int ks = 0; ks < 4; ks++) {        // 4 x k16 per 64-ci chunk
            unsigned bf[4][2];
            #pragma unroll
            for (int nt = 0; nt < 4; nt++) {
                uint32_t base = (wn*32 + nt*8 + g)*128 + ks*32 + tg*4;
                bf[nt][0] = lds32(stgB + SW128(base));
                bf[nt][1] = lds32(stgB + SW128(base + 16));
            }
            #pragma unroll
            for (int mt = 0; mt < 2; mt++) {
                unsigned af[4];
                uint32_t base = (wm*32 + mt*16 + g)*128 + ks*32 + tg*4;
                af[0] = lds32(stgA + SW128(base));
                af[1] = lds32(stgA + SW128(base + 8*128));
                af[2] = lds32(stgA + SW128(base + 16));
                af[3] = lds32(stgA + SW128(base + 8*128 + 16));
                #pragma unroll
                for (int nt = 0; nt < 4; nt++)
                    hmma16816(acc[mt][nt], af, bf[nt]);
            }
        }
        __syncthreads();
    }

    // ---- epilogue: 4 passes, stage [32co][132px] in smem, coalesced stores ----
    float dq = g_dq;
    int px = tid & 127, rro = tid >> 7;         // rro 0..3
    bool pv = (p0 + px) < NPIX;
    float* obase = out + ((size_t)bimg*COUT + coBase)*NPIX + p0 + px;

    #pragma unroll
    for (int pass = 0; pass < 4; pass++) {
        if (wn == pass) {
            #pragma unroll
            for (int mt = 0; mt < 2; mt++) {
                int px0 = wm*32 + mt*16 + g;
                #pragma unroll
                for (int nt = 0; nt < 4; nt++) {
                    int cl = nt*8 + tg*2;
                    s_out[cl*132 + px0]         = acc[mt][nt][0] * dq;
                    s_out[(cl+1)*132 + px0]     = acc[mt][nt][1] * dq;
                    s_out[cl*132 + px0 + 8]     = acc[mt][nt][2] * dq;
                    s_out[(cl+1)*132 + px0 + 8] = acc[mt][nt][3] * dq;
                }
            }
        }
        __syncthreads();
        if (pv) {
            #pragma unroll
            for (int it = 0; it < 8; it++) {
                int row = it*4 + rro;
                int co = pass*32 + row;
                obase[(size_t)co * NPIX] = s_out[row*132 + px] + __ldg(&bias[coBase + co]);
            }
        }
        __syncthreads();
    }
}

// ---------------- launch ------------------------------------------------------
extern "C" void kernel_launch(void* const* d_in, const int* in_sizes, int n_in,
                              void* d_out, int out_size) {
    const float* x    = (const float*)d_in[0];
    const float* wt   = (const float*)d_in[1];
    const float* bias = (const float*)d_in[2];
    float* out = (float*)d_out;

    cudaFuncSetAttribute(k_conv, cudaFuncAttributeMaxDynamicSharedMemorySize, SMEM_TOTAL);

    k_part<<<1088, 256>>>((const float4*)x, (const float4*)wt);   // idx 0
    k_quant_w<<<288, 256>>>(wt);                                  // idx 1
    k_quant_x<<<BATCH*HP, 256>>>(x);                              // idx 2
    dim3 grid(25, 2, BATCH);
    k_conv<<<grid, 512, SMEM_TOTAL>>>(bias, out);                 // idx 3 (ncu)
    (void)in_sizes; (void)n_in; (void)out_size;
}

// round 13
// speedup vs baseline: 1.4683x; 1.3139x over previous
#include <cuda_runtime.h>
#include <cuda_fp16.h>
#include <stdint.h>

#define BATCH 32
#define CIN   128
#define HH    56
#define WW    56
#define COUT  256
#define HP    58
#define NPIX  (HH*WW)            // 3136
#define IMGB  (HP*HP*CIN)        // padded image elements

// ---------------- scratch (device globals) ----------------------------------
__device__ __half g_qx[BATCH*HP*HP*CIN];   // padded NHWC, quantized ints as fp16
// B pre-fragmented: [chunk=tap*2+kh2][cohalf][8192 fp16] (16KB per sub-chunk)
__device__ __half g_qw[18*2*8192];
__device__ float  g_px[1024];
__device__ float  g_pw[64];
__device__ float  g_scale_x, g_dq;

// ---------------- helpers -----------------------------------------------------
__device__ __forceinline__ uint32_t smem_u32(const void* p) {
    uint32_t a;
    asm("{ .reg .u64 t; cvta.to.shared.u64 t, %1; cvt.u32.u64 %0, t; }" : "=r"(a) : "l"(p));
    return a;
}
#define SW128(o) ((o) ^ (((o) >> 3) & 0x70))

__device__ __forceinline__ void cp16(uint32_t dst, const void* src) {
    asm volatile("cp.async.cg.shared.global [%0], [%1], 16;" :: "r"(dst), "l"(src) : "memory");
}
#define CP_COMMIT()  asm volatile("cp.async.commit_group;" ::: "memory")
#define CP_WAIT(n)   asm volatile("cp.async.wait_group %0;" :: "n"(n) : "memory")

__device__ __forceinline__ unsigned lds32(uint32_t a) {
    unsigned v; asm volatile("ld.shared.b32 %0, [%1];" : "=r"(v) : "r"(a)); return v;
}
__device__ __forceinline__ void lds128(unsigned* r, uint32_t a) {
    asm volatile("ld.shared.v4.b32 {%0,%1,%2,%3}, [%4];"
        : "=r"(r[0]), "=r"(r[1]), "=r"(r[2]), "=r"(r[3]) : "r"(a));
}

// fp16 HMMA: m16n8k16, A row-major, B col-major, f32 accumulate
__device__ __forceinline__ void hmma16816(float* d, const unsigned* a, const unsigned* b) {
    asm volatile("mma.sync.aligned.m16n8k16.row.col.f32.f16.f16.f32 "
        "{%0,%1,%2,%3}, {%4,%5,%6,%7}, {%8,%9}, {%0,%1,%2,%3};"
        : "+f"(d[0]), "+f"(d[1]), "+f"(d[2]), "+f"(d[3])
        : "r"(a[0]), "r"(a[1]), "r"(a[2]), "r"(a[3]), "r"(b[0]), "r"(b[1]));
}

__device__ __forceinline__ float warp_red_max(float m) {
    #pragma unroll
    for (int o = 16; o; o >>= 1) m = fmaxf(m, __shfl_xor_sync(0xffffffffu, m, o));
    return m;
}

// ---------------- 0: partial amax --------------------------------------------
__global__ void k_part(const float4* __restrict__ x, const float4* __restrict__ w) {
    int blk = blockIdx.x;
    const float4* p; int n4, stride, start;
    if (blk < 1024) { p = x; n4 = BATCH*CIN*HH*WW/4; start = blk*256 + threadIdx.x; stride = 1024*256; }
    else            { p = w; n4 = COUT*CIN*9/4;      start = (blk-1024)*256 + threadIdx.x; stride = 64*256; }
    float m = 0.f;
    for (int i = start; i < n4; i += stride) {
        float4 v = p[i];
        m = fmaxf(m, fmaxf(fmaxf(fabsf(v.x), fabsf(v.y)), fmaxf(fabsf(v.z), fabsf(v.w))));
    }
    m = warp_red_max(m);
    __shared__ float sm[8];
    int lane = threadIdx.x & 31, wid = threadIdx.x >> 5;
    if (lane == 0) sm[wid] = m;
    __syncthreads();
    if (wid == 0) {
        m = (lane < 8) ? sm[lane] : 0.f;
        m = warp_red_max(m);
        if (lane == 0) { if (blk < 1024) g_px[blk] = m; else g_pw[blk-1024] = m; }
    }
}

// ---------------- 1: finalize scales + quantize weights into FRAGMENT layout --
// g_qw element index o: sub = o>>13 (36 sub-chunks of 8192), f = o&8191.
// nc = sub>>1 (tap*2+kh2), cohalf = sub&1.
// f = (((wn*4+ks)*4 + j)*32 + lane)*8 + e
// co = cohalf*128 + wn*64 + j*16 + (lane>>2) + ((e&4)?8:0)
// ci = (nc&1)*64 + ks*16 + ((e>>1)&1)*8 + (lane&3)*2 + (e&1)
__global__ void k_quant_w(const float* __restrict__ wt) {
    __shared__ float s_sw;
    {
        float mx = 0.f, mw = 0.f;
        for (int i = threadIdx.x; i < 1024; i += blockDim.x) mx = fmaxf(mx, g_px[i]);
        if (threadIdx.x < 64) mw = g_pw[threadIdx.x];
        mx = warp_red_max(mx); mw = warp_red_max(mw);
        __shared__ float smx[8], smw[8];
        int lane = threadIdx.x & 31, wid = threadIdx.x >> 5;
        if (lane == 0) { smx[wid] = mx; smw[wid] = mw; }
        __syncthreads();
        if (threadIdx.x == 0) {
            float ax = 0.f, aw = 0.f;
            #pragma unroll
            for (int i = 0; i < 8; i++) { ax = fmaxf(ax, smx[i]); aw = fmaxf(aw, smw[i]); }
            float sx = __fdiv_rn(127.0f, ax);
            float sw = __fdiv_rn(127.0f, aw);
            s_sw = sw;
            if (blockIdx.x == 0) {
                g_scale_x = sx;
                g_dq = __fdiv_rn(1.0f, __fmul_rn(sx, sw));
            }
        }
        __syncthreads();
    }
    float sc = s_sw;
    const int n = 18*2*8192;
    for (int o = blockIdx.x*blockDim.x + threadIdx.x; o < n; o += gridDim.x*blockDim.x) {
        int f = o & 8191, sub = o >> 13;
        int nc = sub >> 1, cohalf = sub & 1;
        int tap = nc >> 1, kh2 = nc & 1;
        int e = f & 7, lane = (f >> 3) & 31;
        int j = (f >> 8) & 3, ks = (f >> 10) & 3, wn = (f >> 12) & 1;
        int co = cohalf*128 + wn*64 + j*16 + (lane >> 2) + ((e & 4) ? 8 : 0);
        int ci = kh2*64 + ks*16 + ((e >> 1) & 1)*8 + (lane & 3)*2 + (e & 1);
        float q = rintf(wt[(co*CIN + ci)*9 + tap] * sc);
        q = fminf(fmaxf(q, -127.f), 127.f);
        g_qw[o] = __float2half_rn(q);
    }
}

// ---------------- 2: quantize x into padded NHWC (store fp16) -----------------
__global__ void k_quant_x(const float* __restrict__ x) {
    int b = blockIdx.x / HP, hp = blockIdx.x % HP;
    __half* dst = g_qx + ((size_t)b*HP + hp)*HP*CIN;
    if (hp == 0 || hp == HP-1) {
        for (int e = threadIdx.x; e < HP*CIN/8; e += blockDim.x)
            ((int4*)dst)[e] = make_int4(0,0,0,0);
        return;
    }
    int h = hp - 1;
    __shared__ __half s[CIN][60];
    float sc = g_scale_x;
    const float* base = x + ((size_t)b*CIN*HH + h)*WW;
    for (int e = threadIdx.x; e < CIN*WW; e += blockDim.x) {
        int c = e / WW, w = e - c*WW;
        float q = rintf(base[(size_t)c*HH*WW + w] * sc);
        q = fminf(fmaxf(q, -127.f), 127.f);
        s[c][w] = __float2half_rn(q);
    }
    __syncthreads();
    for (int e = threadIdx.x; e < HP*CIN; e += blockDim.x) {
        int wp = e >> 7, c = e & 127;
        dst[e] = (wp == 0 || wp == HP-1) ? __float2half_rn(0.f) : s[c][wp-1];
    }
}

// ---------------- 3: fp16 HMMA conv, 3-stage pipeline, fragment-B -------------
// CTA: 128 px x 128 co, 256 thr = 8 warps (4m x 2n); warp tile 32px x 64co.
// 18 chunks of 64 ci. Stage 32KB = A(16K, SW128) + B(16K, fragment-linear).
// 3 stages, prefetch distance 2, ONE syncthreads per chunk.
// Per ks: 4 LDS.128 (B frags) + 8 LDS.32 (A) + 16 HMMA.
#define STAGE 32768
#define SMEM_TOTAL (3*STAGE)

__global__ void __launch_bounds__(256, 2) k_conv(const float* __restrict__ bias,
                                                 float* __restrict__ out) {
    extern __shared__ char smem[];
    uint32_t sb = smem_u32(smem);
    float* s_out = (float*)smem;

    int tid = threadIdx.x;
    int wid = tid >> 5, lane = tid & 31;
    int wm = wid & 3, wn = wid >> 2;            // 4 x 2 warp grid
    int g = lane >> 2, tg = lane & 3;

    int tile   = blockIdx.x;                    // 0..24
    int cohalf = blockIdx.y;                    // 0 or 1
    int coBase = cohalf << 7;
    int bimg   = blockIdx.z;
    int p0 = tile * 128;

    // producers: A: thread t -> row r=t>>1, 4x16B at (t&1)*4 (SW128)
    //            B: thread t -> 4x16B linear at t*64
    int r = tid >> 1, s4 = (tid & 1) << 2;
    int p = min(p0 + r, NPIX-1);
    int ph = p / WW, pw = p - ph*WW;
    const __half* qb = g_qx + (size_t)bimg * IMGB;
    const __half* abase = qb + (ph*HP + pw)*CIN;
    uint32_t dA[4];
    #pragma unroll
    for (int i = 0; i < 4; i++) dA[i] = SW128((uint32_t)(r*128 + (s4+i)*16));
    uint32_t dB = 16384u + (uint32_t)tid*64;
    const __half* wfrag = g_qw + (size_t)cohalf*8192 + (size_t)tid*32;  // + nc*16384

    float acc[2][8][4];
    #pragma unroll
    for (int mt = 0; mt < 2; mt++)
        #pragma unroll
        for (int nt = 0; nt < 8; nt++)
            #pragma unroll
            for (int q = 0; q < 4; q++) acc[mt][nt][q] = 0.f;

    // B consumer base (linear fragment layout): + ks*2048 + j*512
    uint32_t bBase = 16384u + (uint32_t)wn*8192 + (uint32_t)lane*16;

    // ---- prefetch chunks 0 and 1 ----
    #pragma unroll
    for (int pc = 0; pc < 2; pc++) {
        int tap = pc >> 1, kh2 = pc & 1;
        int dh = tap / 3, dw = tap - dh*3;
        const __half* as = abase + (dh*HP + dw)*CIN + kh2*64;
        const __half* ws = wfrag + (size_t)pc*16384;
        uint32_t stg = sb + pc*STAGE;
        #pragma unroll
        for (int i = 0; i < 4; i++) {
            cp16(stg + dA[i], as + (s4+i)*8);
            cp16(stg + dB + i*16, ws + i*8);
        }
        CP_COMMIT();
    }

    for (int ch = 0; ch < 18; ch++) {
        if (ch < 17) { CP_WAIT(1); } else { CP_WAIT(0); }
        __syncthreads();

        // prefetch ch+2 (stage (ch+2)%3 == stage consumed at ch-1: safe post-sync)
        if (ch + 2 < 18) {
            int nc = ch + 2;
            int tap = nc >> 1, kh2 = nc & 1;
            int dh = tap / 3, dw = tap - dh*3;
            const __half* as = abase + (dh*HP + dw)*CIN + kh2*64;
            const __half* ws = wfrag + (size_t)nc*16384;
            uint32_t stg = sb + (nc % 3)*STAGE;
            #pragma unroll
            for (int i = 0; i < 4; i++) {
                cp16(stg + dA[i], as + (s4+i)*8);
                cp16(stg + dB + i*16, ws + i*8);
            }
            CP_COMMIT();
        }

        uint32_t stgA = sb + (ch % 3)*STAGE;
        uint32_t stgB = stgA + bBase;
        #pragma unroll
        for (int ks = 0; ks < 4; ks++) {
            unsigned bf[4][4];                  // [j][nt2j.b0, b1, nt2j+1.b0, b1]
            #pragma unroll
            for (int j = 0; j < 4; j++)
                lds128(bf[j], stgB + (uint32_t)(ks*2048 + j*512));
            #pragma unroll
            for (int mt = 0; mt < 2; mt++) {
                unsigned af[4];
                uint32_t base = (wm*32 + mt*16 + g)*128 + ks*32 + tg*4;
                af[0] = lds32(stgA + SW128(base));
                af[1] = lds32(stgA + SW128(base + 8*128));
                af[2] = lds32(stgA + SW128(base + 16));
                af[3] = lds32(stgA + SW128(base + 8*128 + 16));
                #pragma unroll
                for (int j = 0; j < 4; j++) {
                    hmma16816(acc[mt][2*j],     af, &bf[j][0]);
                    hmma16816(acc[mt][2*j + 1], af, &bf[j][2]);
                }
            }
        }
        __syncthreads();
    }

    // ---- epilogue: stage [64co][132px] in smem, coalesced dequant+bias stores
    float dq = g_dq;
    int rro = tid >> 7;             // 0..1
    int px = tid & 127;
    bool pv = (p0 + px) < NPIX;
    float* obase = out + ((size_t)bimg*COUT + coBase)*NPIX + p0 + px;

    #pragma unroll
    for (int pass = 0; pass < 2; pass++) {
        if (wn == pass) {
            #pragma unroll
            for (int mt = 0; mt < 2; mt++) {
                int px0 = wm*32 + mt*16 + g;
                #pragma unroll
                for (int nt = 0; nt < 8; nt++) {
                    int cl = nt*8 + tg*2;
                    s_out[cl*132 + px0]         = acc[mt][nt][0] * dq;
                    s_out[(cl+1)*132 + px0]     = acc[mt][nt][1] * dq;
                    s_out[cl*132 + px0 + 8]     = acc[mt][nt][2] * dq;
                    s_out[(cl+1)*132 + px0 + 8] = acc[mt][nt][3] * dq;
                }
            }
        }
        __syncthreads();
        if (pv) {
            #pragma unroll 8
            for (int it = 0; it < 32; it++) {
                int row = it*2 + rro;
                int co = pass*64 + row;
                obase[(size_t)co * NPIX] = s_out[row*132 + px] + __ldg(&bias[coBase + co]);
            }
        }
        __syncthreads();
    }
}

// ---------------- launch ------------------------------------------------------
extern "C" void kernel_launch(void* const* d_in, const int* in_sizes, int n_in,
                              void* d_out, int out_size) {
    const float* x    = (const float*)d_in[0];
    const float* wt   = (const float*)d_in[1];
    const float* bias = (const float*)d_in[2];
    float* out = (float*)d_out;

    cudaFuncSetAttribute(k_conv, cudaFuncAttributeMaxDynamicSharedMemorySize, SMEM_TOTAL);

    k_part<<<1088, 256>>>((const float4*)x, (const float4*)wt);   // idx 0
    k_quant_w<<<288, 256>>>(wt);                                  // idx 1
    k_quant_x<<<BATCH*HP, 256>>>(x);                              // idx 2
    dim3 grid(25, 2, BATCH);
    k_conv<<<grid, 256, SMEM_TOTAL>>>(bias, out);                 // idx 3 (ncu)
    (void)in_sizes; (void)n_in; (void)out_size;
}

// round 14
// speedup vs baseline: 1.6410x; 1.1176x over previous
#include <cuda_runtime.h>
#include <cuda_fp16.h>
#include <stdint.h>

#define BATCH 32
#define CIN   128
#define HH    56
#define WW    56
#define COUT  256
#define HP    58
#define NPIX  (HH*WW)            // 3136
#define IMGB  (HP*HP*CIN)        // padded image elements

// ---------------- scratch (device globals) ----------------------------------
__device__ __half g_qx[BATCH*HP*HP*CIN];   // padded NHWC, quantized ints as fp16
// B pre-fragmented: [chunk=tap*2+kh2][cohalf][8192 fp16] (16KB per sub-chunk)
__device__ __half g_qw[18*2*8192];
__device__ float  g_px[1024];
__device__ float  g_pw[64];
__device__ float  g_scale_x, g_dq;

// ---------------- helpers -----------------------------------------------------
__device__ __forceinline__ uint32_t smem_u32(const void* p) {
    uint32_t a;
    asm("{ .reg .u64 t; cvta.to.shared.u64 t, %1; cvt.u32.u64 %0, t; }" : "=r"(a) : "l"(p));
    return a;
}
#define SW128(o) ((o) ^ (((o) >> 3) & 0x70))

__device__ __forceinline__ void cp16(uint32_t dst, const void* src) {
    asm volatile("cp.async.cg.shared.global [%0], [%1], 16;" :: "r"(dst), "l"(src) : "memory");
}
#define CP_COMMIT()  asm volatile("cp.async.commit_group;" ::: "memory")
#define CP_WAIT(n)   asm volatile("cp.async.wait_group %0;" :: "n"(n) : "memory")

__device__ __forceinline__ unsigned lds32(uint32_t a) {
    unsigned v; asm volatile("ld.shared.b32 %0, [%1];" : "=r"(v) : "r"(a)); return v;
}

// fp16 HMMA: m16n8k16, A row-major, B col-major, f32 accumulate
__device__ __forceinline__ void hmma16816(float* d, const unsigned* a, const unsigned* b) {
    asm volatile("mma.sync.aligned.m16n8k16.row.col.f32.f16.f16.f32 "
        "{%0,%1,%2,%3}, {%4,%5,%6,%7}, {%8,%9}, {%0,%1,%2,%3};"
        : "+f"(d[0]), "+f"(d[1]), "+f"(d[2]), "+f"(d[3])
        : "r"(a[0]), "r"(a[1]), "r"(a[2]), "r"(a[3]), "r"(b[0]), "r"(b[1]));
}

__device__ __forceinline__ float warp_red_max(float m) {
    #pragma unroll
    for (int o = 16; o; o >>= 1) m = fmaxf(m, __shfl_xor_sync(0xffffffffu, m, o));
    return m;
}

// ---------------- 0: partial amax --------------------------------------------
__global__ void k_part(const float4* __restrict__ x, const float4* __restrict__ w) {
    int blk = blockIdx.x;
    const float4* p; int n4, stride, start;
    if (blk < 1024) { p = x; n4 = BATCH*CIN*HH*WW/4; start = blk*256 + threadIdx.x; stride = 1024*256; }
    else            { p = w; n4 = COUT*CIN*9/4;      start = (blk-1024)*256 + threadIdx.x; stride = 64*256; }
    float m = 0.f;
    for (int i = start; i < n4; i += stride) {
        float4 v = p[i];
        m = fmaxf(m, fmaxf(fmaxf(fabsf(v.x), fabsf(v.y)), fmaxf(fabsf(v.z), fabsf(v.w))));
    }
    m = warp_red_max(m);
    __shared__ float sm[8];
    int lane = threadIdx.x & 31, wid = threadIdx.x >> 5;
    if (lane == 0) sm[wid] = m;
    __syncthreads();
    if (wid == 0) {
        m = (lane < 8) ? sm[lane] : 0.f;
        m = warp_red_max(m);
        if (lane == 0) { if (blk < 1024) g_px[blk] = m; else g_pw[blk-1024] = m; }
    }
}

// ---------------- 1: finalize scales + quantize weights into FRAGMENT layout --
// g_qw element index o: sub = o>>13, f = o&8191; nc = sub>>1, cohalf = sub&1.
// f = (((wn*4+ks)*4 + j)*32 + lane)*8 + e
// co = cohalf*128 + wn*64 + j*16 + (lane>>2) + ((e&4)?8:0)
// ci = (nc&1)*64 + ks*16 + ((e>>1)&1)*8 + (lane&3)*2 + (e&1)
__global__ void k_quant_w(const float* __restrict__ wt) {
    __shared__ float s_sw;
    {
        float mx = 0.f, mw = 0.f;
        for (int i = threadIdx.x; i < 1024; i += blockDim.x) mx = fmaxf(mx, g_px[i]);
        if (threadIdx.x < 64) mw = g_pw[threadIdx.x];
        mx = warp_red_max(mx); mw = warp_red_max(mw);
        __shared__ float smx[8], smw[8];
        int lane = threadIdx.x & 31, wid = threadIdx.x >> 5;
        if (lane == 0) { smx[wid] = mx; smw[wid] = mw; }
        __syncthreads();
        if (threadIdx.x == 0) {
            float ax = 0.f, aw = 0.f;
            #pragma unroll
            for (int i = 0; i < 8; i++) { ax = fmaxf(ax, smx[i]); aw = fmaxf(aw, smw[i]); }
            float sx = __fdiv_rn(127.0f, ax);
            float sw = __fdiv_rn(127.0f, aw);
            s_sw = sw;
            if (blockIdx.x == 0) {
                g_scale_x = sx;
                g_dq = __fdiv_rn(1.0f, __fmul_rn(sx, sw));
            }
        }
        __syncthreads();
    }
    float sc = s_sw;
    const int n = 18*2*8192;
    for (int o = blockIdx.x*blockDim.x + threadIdx.x; o < n; o += gridDim.x*blockDim.x) {
        int f = o & 8191, sub = o >> 13;
        int nc = sub >> 1, cohalf = sub & 1;
        int tap = nc >> 1, kh2 = nc & 1;
        int e = f & 7, lane = (f >> 3) & 31;
        int j = (f >> 8) & 3, ks = (f >> 10) & 3, wn = (f >> 12) & 1;
        int co = cohalf*128 + wn*64 + j*16 + (lane >> 2) + ((e & 4) ? 8 : 0);
        int ci = kh2*64 + ks*16 + ((e >> 1) & 1)*8 + (lane & 3)*2 + (e & 1);
        float q = rintf(wt[(co*CIN + ci)*9 + tap] * sc);
        q = fminf(fmaxf(q, -127.f), 127.f);
        g_qw[o] = __float2half_rn(q);
    }
}

// ---------------- 2: quantize x into padded NHWC (store fp16) -----------------
__global__ void k_quant_x(const float* __restrict__ x) {
    int b = blockIdx.x / HP, hp = blockIdx.x % HP;
    __half* dst = g_qx + ((size_t)b*HP + hp)*HP*CIN;
    if (hp == 0 || hp == HP-1) {
        for (int e = threadIdx.x; e < HP*CIN/8; e += blockDim.x)
            ((int4*)dst)[e] = make_int4(0,0,0,0);
        return;
    }
    int h = hp - 1;
    __shared__ __half s[CIN][60];
    float sc = g_scale_x;
    const float* base = x + ((size_t)b*CIN*HH + h)*WW;
    for (int e = threadIdx.x; e < CIN*WW; e += blockDim.x) {
        int c = e / WW, w = e - c*WW;
        float q = rintf(base[(size_t)c*HH*WW + w] * sc);
        q = fminf(fmaxf(q, -127.f), 127.f);
        s[c][w] = __float2half_rn(q);
    }
    __syncthreads();
    for (int e = threadIdx.x; e < HP*CIN; e += blockDim.x) {
        int wp = e >> 7, c = e & 127;
        dst[e] = (wp == 0 || wp == HP-1) ? __float2half_rn(0.f) : s[c][wp-1];
    }
}

// ---------------- 3: fp16 HMMA conv — A smem-pipelined, B reg-prefetched LDG --
// CTA: 128 px x 128 co, 256 thr = 8 warps (4m x 2n); warp tile 32px x 64co.
// 18 chunks of 64 ci. A: 3 stages x 16KB SW128, cp.async dist 2, 1 sync/chunk.
// B: direct LDG.128 from fragment-layout gmem (L1/L2-resident), double-buffered
// one k16-step ahead in registers. Per ks: 8 LDS.32 (A) + 4 LDG.128 (B) + 16 HMMA.
#define STAGE 16384
#define SMEM_TOTAL (3*STAGE)

__global__ void __launch_bounds__(256, 2) k_conv(const float* __restrict__ bias,
                                                 float* __restrict__ out) {
    extern __shared__ char smem[];
    uint32_t sb = smem_u32(smem);
    float* s_out = (float*)smem;

    int tid = threadIdx.x;
    int wid = tid >> 5, lane = tid & 31;
    int wm = wid & 3, wn = wid >> 2;            // 4 x 2 warp grid
    int g = lane >> 2, tg = lane & 3;

    int tile   = blockIdx.x;                    // 0..24
    int cohalf = blockIdx.y;                    // 0 or 1
    int coBase = cohalf << 7;
    int bimg   = blockIdx.z;
    int p0 = tile * 128;

    // A producer: thread t -> row r=t>>1, 4x16B at (t&1)*4 (SW128)
    int r = tid >> 1, s4 = (tid & 1) << 2;
    int p = min(p0 + r, NPIX-1);
    int ph = p / WW, pw = p - ph*WW;
    const __half* qb = g_qx + (size_t)bimg * IMGB;
    const __half* abase = qb + (ph*HP + pw)*CIN;
    uint32_t dA[4];
    #pragma unroll
    for (int i = 0; i < 4; i++) dA[i] = SW128((uint32_t)(r*128 + (s4+i)*16));

    // B per-warp fragment pointer (int4 units): idx = nc*2048 + ks*128 + j*32
    const int4* bbase = (const int4*)g_qw + cohalf*1024 + wn*512 + lane;

    float acc[2][8][4];
    #pragma unroll
    for (int mt = 0; mt < 2; mt++)
        #pragma unroll
        for (int nt = 0; nt < 8; nt++)
            #pragma unroll
            for (int q = 0; q < 4; q++) acc[mt][nt][q] = 0.f;

    // ---- prefetch A chunks 0 and 1 ----
    #pragma unroll
    for (int pc = 0; pc < 2; pc++) {
        int tap = pc >> 1, kh2 = pc & 1;
        int dh = tap / 3, dw = tap - dh*3;
        const __half* as = abase + (dh*HP + dw)*CIN + kh2*64;
        uint32_t stg = sb + pc*STAGE;
        #pragma unroll
        for (int i = 0; i < 4; i++) cp16(stg + dA[i], as + (s4+i)*8);
        CP_COMMIT();
    }

    // ---- prefetch B fragments for (chunk 0, ks 0) ----
    int4 bfr[2][4];
    #pragma unroll
    for (int j = 0; j < 4; j++) bfr[0][j] = __ldg(bbase + j*32);

    for (int ch = 0; ch < 18; ch++) {
        if (ch < 17) { CP_WAIT(1); } else { CP_WAIT(0); }
        __syncthreads();

        // prefetch A chunk ch+2 into stage (ch+2)%3 (safe: consumers of that
        // stage finished before the sync above)
        if (ch + 2 < 18) {
            int nc = ch + 2;
            int tap = nc >> 1, kh2 = nc & 1;
            int dh = tap / 3, dw = tap - dh*3;
            const __half* as = abase + (dh*HP + dw)*CIN + kh2*64;
            uint32_t stg = sb + (nc % 3)*STAGE;
            #pragma unroll
            for (int i = 0; i < 4; i++) cp16(stg + dA[i], as + (s4+i)*8);
            CP_COMMIT();
        }

        uint32_t stgA = sb + (ch % 3)*STAGE;
        #pragma unroll
        for (int ks = 0; ks < 4; ks++) {
            // prefetch next k16-step's B fragments (may cross chunk boundary)
            int kb1 = ch*4 + ks + 1;
            if (kb1 < 72) {
                int nc = kb1 >> 2, nks = kb1 & 3;
                #pragma unroll
                for (int j = 0; j < 4; j++)
                    bfr[(ks + 1) & 1][j] = __ldg(bbase + nc*2048 + nks*128 + j*32);
            }
            const unsigned* bfp = (const unsigned*)&bfr[ks & 1][0];
            #pragma unroll
            for (int mt = 0; mt < 2; mt++) {
                unsigned af[4];
                uint32_t base = (wm*32 + mt*16 + g)*128 + ks*32 + tg*4;
                af[0] = lds32(stgA + SW128(base));
                af[1] = lds32(stgA + SW128(base + 8*128));
                af[2] = lds32(stgA + SW128(base + 16));
                af[3] = lds32(stgA + SW128(base + 8*128 + 16));
                #pragma unroll
                for (int j = 0; j < 4; j++) {
                    hmma16816(acc[mt][2*j],     af, bfp + j*4);
                    hmma16816(acc[mt][2*j + 1], af, bfp + j*4 + 2);
                }
            }
        }
        // no bottom sync: next iteration's top sync orders stage reuse
    }
    __syncthreads();   // protect s_out overlay of stage smem

    // ---- epilogue: stage [64co][132px] in smem, coalesced dequant+bias stores
    float dq = g_dq;
    int rro = tid >> 7;             // 0..1
    int px = tid & 127;
    bool pv = (p0 + px) < NPIX;
    float* obase = out + ((size_t)bimg*COUT + coBase)*NPIX + p0 + px;

    #pragma unroll
    for (int pass = 0; pass < 2; pass++) {
        if (wn == pass) {
            #pragma unroll
            for (int mt = 0; mt < 2; mt++) {
                int px0 = wm*32 + mt*16 + g;
                #pragma unroll
                for (int nt = 0; nt < 8; nt++) {
                    int cl = nt*8 + tg*2;
                    s_out[cl*132 + px0]         = acc[mt][nt][0] * dq;
                    s_out[(cl+1)*132 + px0]     = acc[mt][nt][1] * dq;
                    s_out[cl*132 + px0 + 8]     = acc[mt][nt][2] * dq;
                    s_out[(cl+1)*132 + px0 + 8] = acc[mt][nt][3] * dq;
                }
            }
        }
        __syncthreads();
        if (pv) {
            #pragma unroll 8
            for (int it = 0; it < 32; it++) {
                int row = it*2 + rro;
                int co = pass*64 + row;
                obase[(size_t)co * NPIX] = s_out[row*132 + px] + __ldg(&bias[coBase + co]);
            }
        }
        __syncthreads();
    }
}

// ---------------- launch ------------------------------------------------------
extern "C" void kernel_launch(void* const* d_in, const int* in_sizes, int n_in,
                              void* d_out, int out_size) {
    const float* x    = (const float*)d_in[0];
    const float* wt   = (const float*)d_in[1];
    const float* bias = (const float*)d_in[2];
    float* out = (float*)d_out;

    cudaFuncSetAttribute(k_conv, cudaFuncAttributeMaxDynamicSharedMemorySize, SMEM_TOTAL);

    k_part<<<1088, 256>>>((const float4*)x, (const float4*)wt);   // idx 0
    k_quant_w<<<288, 256>>>(wt);                                  // idx 1
    k_quant_x<<<BATCH*HP, 256>>>(x);                              // idx 2
    dim3 grid(25, 2, BATCH);
    k_conv<<<grid, 256, SMEM_TOTAL>>>(bias, out);                 // idx 3 (ncu)
    (void)in_sizes; (void)n_in; (void)out_size;
}